// round 3
// baseline (speedup 1.0000x reference)
#include <cuda_runtime.h>
#include <cstdint>

// Problem constants (from reference): C=1000, N=256, D=512, B=4096
#define CC 1000
#define NN 256
#define DD 512
#define BB 4096

#define ROWS_PER_BLOCK 16         // 16 rows * 2KB = 32KB per block
#define GATHER_THREADS 256        // 8 warps, 2 rows per warp, 8 float4/thread

// Scratch (no allocations allowed). Static zero-init: 0 means "no push".
__device__ int g_last_pos1[CC];   // last valid batch pos + 1 per class; 0 = none
__device__ int g_src[CC * NN];    // global source row per output row:
                                  //   >=0 : row index into memory  [C*N)
                                  //   <0  : ~idx = row index into batch_features

// ---------------------------------------------------------------------------
// Kernel 1: per batch item, first-occurrence argmax over the int32 targets row
// (values are tiny, ties common -> must keep FIRST max), validity check, then
// atomicMax of (pos+1) into the class slot (last valid write wins).
// One warp per item; int4-vectorized row scan (1000 ints = 250 aligned int4).
__global__ void k_select(const int* __restrict__ tgt,
                         const float* __restrict__ bconf,
                         const int* __restrict__ mask,
                         const float* __restrict__ conf) {
    int warp = (blockIdx.x * blockDim.x + threadIdx.x) >> 5;
    int lane = threadIdx.x & 31;
    if (warp >= BB) return;
    if (mask[warp] == 0) return;   // uniform across the warp (same item)

    const int4* row = (const int4*)(tgt + (long long)warp * CC);  // 250 int4
    int bestv = -2147483647 - 1;
    int besti = CC;
    // per-lane traversal is in increasing index order -> strict '>' keeps
    // the first occurrence of the max
    for (int j = lane; j < CC / 4; j += 32) {
        int4 q = row[j];
        int base = j * 4;
        if (q.x > bestv) { bestv = q.x; besti = base;     }
        if (q.y > bestv) { bestv = q.y; besti = base + 1; }
        if (q.z > bestv) { bestv = q.z; besti = base + 2; }
        if (q.w > bestv) { bestv = q.w; besti = base + 3; }
    }
    #pragma unroll
    for (int off = 16; off; off >>= 1) {
        int ov = __shfl_down_sync(0xffffffffu, bestv, off);
        int oi = __shfl_down_sync(0xffffffffu, besti, off);
        if (ov > bestv || (ov == bestv && oi < besti)) { bestv = ov; besti = oi; }
    }
    if (lane == 0) {
        int t = besti;
        // validity vs ORIGINAL last-slot confidence of the class
        if (bconf[warp] > conf[t * NN + (NN - 1)]) {
            atomicMax(&g_last_pos1[t], warp + 1);
        }
    }
}

// ---------------------------------------------------------------------------
// Kernel 2: per class, build conf2 (only slot N-1 replaced when updated),
// stable descending argsort via u64 bitonic sort (desc conf, asc index),
// emit per-output-row GLOBAL source row (post-shift mapping).
// Also resets g_last_pos1[c] to 0 so every graph replay starts clean.
__global__ void k_sort(const float* __restrict__ conf,
                       const float* __restrict__ bconf) {
    int c = blockIdx.x;
    int t = threadIdx.x;   // 256 threads, one per slot
    __shared__ unsigned long long key[NN];

    int lp1 = g_last_pos1[c];
    bool updated = (lp1 > 0);
    int lp = lp1 - 1;

    float v = (updated && t == NN - 1) ? bconf[lp] : conf[c * NN + t];
    // order-preserving float->uint (ascending), then invert for descending
    unsigned u = __float_as_uint(v);
    u = (u & 0x80000000u) ? ~u : (u | 0x80000000u);
    unsigned inv = ~u;
    key[t] = ((unsigned long long)inv << 32) | (unsigned)t;
    __syncthreads();

    // all threads have read g_last_pos1[c] before this point; safe to reset
    if (t == 0) g_last_pos1[c] = 0;

    // ascending bitonic sort of 256 u64 keys
    for (int k = 2; k <= NN; k <<= 1) {
        for (int j = k >> 1; j > 0; j >>= 1) {
            int ixj = t ^ j;
            if (ixj > t) {
                bool up = ((t & k) == 0);
                unsigned long long a = key[t], b = key[ixj];
                if ((a > b) == up) { key[t] = b; key[ixj] = a; }
            }
            __syncthreads();
        }
    }

    int slot = (int)(key[t] & 0xffffffffu);   // pre-shift slot whose conf sorts here
    int src;
    if (updated) {
        if (slot == NN - 1) src = ~lp;                 // new feature from batch
        else                src = c * NN + slot + 1;   // shifted memory row
    } else {
        src = c * NN + slot;
    }
    g_src[c * NN + t] = src;
}

// ---------------------------------------------------------------------------
// Kernel 3: gather rows. 16 rows per block, 8 warps, each warp owns 2 rows.
// Per thread: 8 independent float4 loads front-batched (MLP=8), then 8 stores.
// Streaming hints: data is use-once.
__global__ void __launch_bounds__(GATHER_THREADS)
k_gather(const float* __restrict__ mem,
         const float* __restrict__ bfeat,
         float* __restrict__ out) {
    const int t    = threadIdx.x;
    const int warp = t >> 5;
    const int lane = t & 31;
    const long long row0 = (long long)blockIdx.x * ROWS_PER_BLOCK + warp * 2;

    int s0 = g_src[row0];
    int s1 = g_src[row0 + 1];
    const float4* a = (const float4*)((s0 >= 0) ? mem   + (long long)s0    * DD
                                                : bfeat + (long long)(~s0) * DD);
    const float4* b = (const float4*)((s1 >= 0) ? mem   + (long long)s1    * DD
                                                : bfeat + (long long)(~s1) * DD);
    float4 v[8];
    #pragma unroll
    for (int p = 0; p < 4; p++) v[p]     = __ldcs(a + lane + p * 32);
    #pragma unroll
    for (int p = 0; p < 4; p++) v[4 + p] = __ldcs(b + lane + p * 32);

    float4* o = (float4*)out + row0 * (DD / 4);
    #pragma unroll
    for (int p = 0; p < 4; p++) __stcs(o + lane + p * 32, v[p]);
    #pragma unroll
    for (int p = 0; p < 4; p++) __stcs(o + (DD / 4) + lane + p * 32, v[4 + p]);
}

// ---------------------------------------------------------------------------
extern "C" void kernel_launch(void* const* d_in, const int* in_sizes, int n_in,
                              void* d_out, int out_size) {
    const float* batch_features    = (const float*)d_in[0];   // [B, D]
    const int*   batch_targets     = (const int*)  d_in[1];   // [B, C] int32
    const float* batch_confidences = (const float*)d_in[2];   // [B]
    const int*   selected_mask     = (const int*)  d_in[3];   // [B]
    const float* memory            = (const float*)d_in[4];   // [C, N, D]
    const float* confidences       = (const float*)d_in[5];   // [C, N]
    float* out = (float*)d_out;                               // [C, N, D]

    k_select<<<(BB * 32) / 256, 256>>>(batch_targets, batch_confidences,
                                       selected_mask, confidences);
    k_sort<<<CC, NN>>>(confidences, batch_confidences);
    k_gather<<<(CC * NN) / ROWS_PER_BLOCK, GATHER_THREADS>>>(memory, batch_features, out);
}